// round 1
// baseline (speedup 1.0000x reference)
#include <cuda_runtime.h>
#include <math.h>

// ---------------------------------------------------------------------------
// Problem: TextEmbedderLETS
//   in[0] x            [B=8, C=7, T=45]        f32
//   in[1] hidden_states[B=8, S=4096, D=5120]   f32   (671 MB -> dominates)
//   in[2] W_proj       [T=45, D=5120]          f32
//   in[3] b_proj       [D=5120]                f32
//   out: e_fused [B, D] followed by x_normalized [B, C, T]  (flattened tuple)
// ---------------------------------------------------------------------------

#define BD 256   // threads per block (both kernels)

// ============================================================================
// Kernel A: per-batch small work.
//   - min/max normalize x over T per (b, c)        -> out_xnorm
//   - series_mean[t] = mean_c x[b,c,t]
//   - emb[d] = sum_t series_mean[t] * W[t,d] + b[d]
//   - L2 normalize emb, write into out_fused[b, :]  (initializes accumulator)
// ============================================================================
__global__ __launch_bounds__(BD) void series_branch_kernel(
    const float* __restrict__ x,
    const float* __restrict__ W,
    const float* __restrict__ bias,
    float* __restrict__ out_fused,
    float* __restrict__ out_xnorm,
    int C, int T, int D)
{
    const int b   = blockIdx.x;
    const int tid = threadIdx.x;

    __shared__ float sx[7 * 45];
    __shared__ float smn[7], smx[7];
    __shared__ float sm[45];
    __shared__ float semb[5120];
    __shared__ float sred[8];
    __shared__ float s_invnorm;

    const int CT = C * T;
    const float* xb = x + (size_t)b * CT;

    for (int i = tid; i < CT; i += BD) sx[i] = xb[i];
    __syncthreads();

    // per-channel min/max (C=7, tiny serial scan per channel)
    if (tid < C) {
        float mn = sx[tid * T], mx = mn;
        for (int t = 1; t < T; t++) {
            float v = sx[tid * T + t];
            mn = fminf(mn, v);
            mx = fmaxf(mx, v);
        }
        smn[tid] = mn;
        smx[tid] = mx;
    }
    __syncthreads();

    // x_normalized
    for (int i = tid; i < CT; i += BD) {
        int c = i / T;
        float v  = sx[i];
        float mn = smn[c], mx = smx[c];
        out_xnorm[(size_t)b * CT + i] = (mx > mn) ? (v - mn) / (mx - mn) : v;
    }

    // series mean over channels
    if (tid < T) {
        float s = 0.f;
        for (int c = 0; c < C; c++) s += sx[c * T + tid];
        sm[tid] = s / (float)C;
    }
    __syncthreads();

    // projection + sum of squares
    float ss = 0.f;
    for (int d = tid; d < D; d += BD) {
        float acc = bias[d];
        #pragma unroll
        for (int t = 0; t < 45; t++)
            acc = fmaf(sm[t], W[(size_t)t * D + d], acc);
        semb[d] = acc;
        ss = fmaf(acc, acc, ss);
    }

    // block reduce ss (8 warps)
    #pragma unroll
    for (int off = 16; off; off >>= 1)
        ss += __shfl_xor_sync(0xffffffffu, ss, off);
    if ((tid & 31) == 0) sred[tid >> 5] = ss;
    __syncthreads();
    if (tid == 0) {
        float tot = 0.f;
        #pragma unroll
        for (int w = 0; w < 8; w++) tot += sred[w];
        s_invnorm = 1.0f / fmaxf(sqrtf(tot), 1e-12f);
    }
    __syncthreads();

    const float inv = s_invnorm;
    for (int d = tid; d < D; d += BD)
        out_fused[(size_t)b * D + d] = semb[d] * inv;
}

// ============================================================================
// Kernel B: mean over S of hidden_states [B, S, D], accumulated into out_fused.
//   grid = (D/4/BD, B, SPLITS). Each thread owns one float4 column of D and
//   sums rows [s0, s0+rows). Coalesced 128B/warp per row. atomicAdd(sum/S).
// ============================================================================
__global__ __launch_bounds__(BD) void mean_pool_kernel(
    const float* __restrict__ hs,
    float* __restrict__ out_fused,
    int S, int D)
{
    const int D4 = D >> 2;
    const int d4 = blockIdx.x * BD + threadIdx.x;
    if (d4 >= D4) return;
    const int b    = blockIdx.y;
    const int rows = S / gridDim.z;
    const int s0   = blockIdx.z * rows;

    const float4* p = reinterpret_cast<const float4*>(hs)
                    + (size_t)b * S * D4 + (size_t)s0 * D4 + d4;

    float4 a0 = make_float4(0.f, 0.f, 0.f, 0.f);
    float4 a1 = make_float4(0.f, 0.f, 0.f, 0.f);

    int r = 0;
    #pragma unroll 4
    for (; r + 1 < rows; r += 2) {
        float4 v0 = __ldg(p + (size_t)r       * D4);
        float4 v1 = __ldg(p + (size_t)(r + 1) * D4);
        a0.x += v0.x; a0.y += v0.y; a0.z += v0.z; a0.w += v0.w;
        a1.x += v1.x; a1.y += v1.y; a1.z += v1.z; a1.w += v1.w;
    }
    for (; r < rows; r++) {
        float4 v = __ldg(p + (size_t)r * D4);
        a0.x += v.x; a0.y += v.y; a0.z += v.z; a0.w += v.w;
    }

    const float inv = 1.0f / (float)S;
    float* o = out_fused + (size_t)b * D + (size_t)d4 * 4;
    atomicAdd(o + 0, (a0.x + a1.x) * inv);
    atomicAdd(o + 1, (a0.y + a1.y) * inv);
    atomicAdd(o + 2, (a0.z + a1.z) * inv);
    atomicAdd(o + 3, (a0.w + a1.w) * inv);
}

// ============================================================================
extern "C" void kernel_launch(void* const* d_in, const int* in_sizes, int n_in,
                              void* d_out, int out_size)
{
    const float* x    = (const float*)d_in[0];
    const float* hs   = (const float*)d_in[1];
    const float* W    = (const float*)d_in[2];
    const float* bias = (const float*)d_in[3];

    const int D = in_sizes[3];                 // 5120
    const int T = in_sizes[2] / D;             // 45
    const int B = 8;
    const int C = in_sizes[0] / (B * T);       // 7
    const int S = in_sizes[1] / (B * D);       // 4096

    float* out_fused = (float*)d_out;                       // [B, D]
    float* out_xnorm = (float*)d_out + (size_t)B * D;       // [B, C, T]

    // Kernel A initializes out_fused with the normalized series embedding
    // and writes x_normalized.
    series_branch_kernel<<<B, BD>>>(x, W, bias, out_fused, out_xnorm, C, T, D);

    // Kernel B accumulates the hidden-state mean on top via atomics.
    const int SPLITS = 16;                     // 5 x 8 x 16 = 640 CTAs, 1 wave
    dim3 grid((D / 4 + BD - 1) / BD, B, SPLITS);
    mean_pool_kernel<<<grid, BD>>>(hs, out_fused, S, D);
}

// round 2
// speedup vs baseline: 2.0159x; 2.0159x over previous
#include <cuda_runtime.h>
#include <math.h>

// ---------------------------------------------------------------------------
// TextEmbedderLETS on GB300
//   in[0] x            [B=8, C=7, T=45]        f32
//   in[1] hidden_states[B=8, S=4096, D=5120]   f32   (671 MB -> the roofline)
//   in[2] W_proj       [T=45, D=5120]          f32
//   in[3] b_proj       [D=5120]                f32
//   out: e_fused [B, D] ++ x_normalized [B, C, T]
//
// R2: series branch split into 3 wide-grid micro-kernels (was one 8-CTA
// kernel costing ~115us). mean_pool raised to 1 full wave @ 6 CTAs/SM.
// ---------------------------------------------------------------------------

#define BD 256
#define B_MAX 8
#define D_DIM 5120
#define T_DIM 45
#define C_DIM 7
#define SPLITS 22   // 5 * 8 * 22 = 880 CTAs ~= 148 SMs * 6 CTAs (one wave)

__device__ float g_sm [B_MAX * T_DIM];   // per-batch channel-mean series
__device__ float g_emb[B_MAX * D_DIM];   // un-normalized projection
__device__ float g_ssq[B_MAX];           // per-batch sum of squares

// ============================================================================
// A1: tiny per-batch prep. grid(B), 64 threads.
//   - min/max normalize x over T per (b,c) -> out_xnorm
//   - sm[b][t] = mean_c x[b,c,t]
//   - zero ssq accumulators (block 0)
// ============================================================================
__global__ __launch_bounds__(64) void prep_kernel(
    const float* __restrict__ x,
    float* __restrict__ out_xnorm,
    int B, int C, int T)
{
    const int b   = blockIdx.x;
    const int tid = threadIdx.x;

    __shared__ float sx[C_DIM * T_DIM];
    __shared__ float smn[C_DIM], smx[C_DIM];

    if (b == 0 && tid < B) g_ssq[tid] = 0.0f;

    const int CT = C * T;
    const float* xb = x + (size_t)b * CT;
    for (int i = tid; i < CT; i += 64) sx[i] = xb[i];
    __syncthreads();

    if (tid < C) {
        float mn = sx[tid * T], mx = mn;
        for (int t = 1; t < T; t++) {
            float v = sx[tid * T + t];
            mn = fminf(mn, v);
            mx = fmaxf(mx, v);
        }
        smn[tid] = mn; smx[tid] = mx;
    }
    __syncthreads();

    for (int i = tid; i < CT; i += 64) {
        int c = i / T;
        float v = sx[i], mn = smn[c], mx = smx[c];
        out_xnorm[(size_t)b * CT + i] = (mx > mn) ? (v - mn) / (mx - mn) : v;
    }

    if (tid < T) {
        float s = 0.f;
        #pragma unroll
        for (int c = 0; c < C_DIM; c++) s += sx[c * T + tid];
        g_sm[b * T_DIM + tid] = s * (1.0f / (float)C);
    }
}

// ============================================================================
// A2: projection for ALL batches. grid(D/BD = 20), 256 threads.
//   Each thread owns one d: loads W[t,d] once, FMAs into 8 batch accumulators.
//   Warp-reduce per-batch squared sums -> atomicAdd(g_ssq[b]).
// ============================================================================
__global__ __launch_bounds__(BD) void project_kernel(
    const float* __restrict__ W,
    const float* __restrict__ bias,
    int B, int T, int D)
{
    const int d   = blockIdx.x * BD + threadIdx.x;
    const int tid = threadIdx.x;

    __shared__ float s_sm[B_MAX * T_DIM];
    for (int i = tid; i < B * T_DIM; i += BD) s_sm[i] = g_sm[i];
    __syncthreads();

    float acc[B_MAX];
    const float bv = bias[d];
    #pragma unroll
    for (int b = 0; b < B_MAX; b++) acc[b] = bv;

    #pragma unroll
    for (int t = 0; t < T_DIM; t++) {
        const float w = W[(size_t)t * D + d];
        #pragma unroll
        for (int b = 0; b < B_MAX; b++)
            acc[b] = fmaf(s_sm[b * T_DIM + t], w, acc[b]);
    }

    #pragma unroll
    for (int b = 0; b < B_MAX; b++) {
        g_emb[(size_t)b * D + d] = acc[b];
        float sq = acc[b] * acc[b];
        #pragma unroll
        for (int off = 16; off; off >>= 1)
            sq += __shfl_xor_sync(0xffffffffu, sq, off);
        if ((tid & 31) == 0) atomicAdd(&g_ssq[b], sq);
    }
}

// ============================================================================
// A3: normalize + init out_fused. grid(20, B), 256 threads.
// ============================================================================
__global__ __launch_bounds__(BD) void norm_init_kernel(
    float* __restrict__ out_fused, int D)
{
    const int d = blockIdx.x * BD + threadIdx.x;
    const int b = blockIdx.y;
    const float inv = 1.0f / fmaxf(sqrtf(g_ssq[b]), 1e-12f);
    out_fused[(size_t)b * D + d] = g_emb[(size_t)b * D + d] * inv;
}

// ============================================================================
// B: mean over S of hidden_states [B,S,D], atomicAdd into out_fused.
//    grid(D/4/BD = 5, B, SPLITS). Streaming loads, one full wave @6 CTAs/SM.
// ============================================================================
__global__ __launch_bounds__(BD, 6) void mean_pool_kernel(
    const float* __restrict__ hs,
    float* __restrict__ out_fused,
    int S, int D)
{
    const int D4 = D >> 2;
    const int d4 = blockIdx.x * BD + threadIdx.x;
    const int b  = blockIdx.y;
    const int z  = blockIdx.z;

    // balanced, possibly non-uniform split of S
    const int s0 = (int)(((long long)z * S) / SPLITS);
    const int s1 = (int)(((long long)(z + 1) * S) / SPLITS);
    const int rows = s1 - s0;

    const float4* p = reinterpret_cast<const float4*>(hs)
                    + (size_t)b * S * D4 + (size_t)s0 * D4 + d4;

    float4 a0 = make_float4(0.f, 0.f, 0.f, 0.f);
    float4 a1 = make_float4(0.f, 0.f, 0.f, 0.f);

    int r = 0;
    #pragma unroll 4
    for (; r + 1 < rows; r += 2) {
        float4 v0 = __ldcs(p + (size_t)r       * D4);
        float4 v1 = __ldcs(p + (size_t)(r + 1) * D4);
        a0.x += v0.x; a0.y += v0.y; a0.z += v0.z; a0.w += v0.w;
        a1.x += v1.x; a1.y += v1.y; a1.z += v1.z; a1.w += v1.w;
    }
    for (; r < rows; r++) {
        float4 v = __ldcs(p + (size_t)r * D4);
        a0.x += v.x; a0.y += v.y; a0.z += v.z; a0.w += v.w;
    }

    const float inv = 1.0f / (float)S;
    float* o = out_fused + (size_t)b * D + (size_t)d4 * 4;
    atomicAdd(o + 0, (a0.x + a1.x) * inv);
    atomicAdd(o + 1, (a0.y + a1.y) * inv);
    atomicAdd(o + 2, (a0.z + a1.z) * inv);
    atomicAdd(o + 3, (a0.w + a1.w) * inv);
}

// ============================================================================
extern "C" void kernel_launch(void* const* d_in, const int* in_sizes, int n_in,
                              void* d_out, int out_size)
{
    const float* x    = (const float*)d_in[0];
    const float* hs   = (const float*)d_in[1];
    const float* W    = (const float*)d_in[2];
    const float* bias = (const float*)d_in[3];

    const int D = in_sizes[3];                 // 5120
    const int T = in_sizes[2] / D;             // 45
    const int B = 8;
    const int C = in_sizes[0] / (B * T);       // 7
    const int S = in_sizes[1] / (B * D);       // 4096

    float* out_fused = (float*)d_out;                  // [B, D]
    float* out_xnorm = (float*)d_out + (size_t)B * D;  // [B, C, T]

    prep_kernel<<<B, 64>>>(x, out_xnorm, B, C, T);
    project_kernel<<<D / BD, BD>>>(W, bias, B, T, D);
    norm_init_kernel<<<dim3(D / BD, B), BD>>>(out_fused, D);

    dim3 grid(D / 4 / BD, B, SPLITS);          // 5 x 8 x 22 = 880 CTAs
    mean_pool_kernel<<<grid, BD>>>(hs, out_fused, S, D);
}

// round 4
// speedup vs baseline: 2.0933x; 1.0384x over previous
#include <cuda_runtime.h>
#include <math.h>

// ---------------------------------------------------------------------------
// TextEmbedderLETS on GB300 — R4 (R3 fusion + s_sm coverage bugfix)
//   20 series CTAs run concurrently with 840 streaming CTAs (860 = one wave).
//   Tiny combine kernel finishes. Critical path ~= stream + 2us.
//   R3 bug: "if (tid < 360)" with 256 threads left s_sm[256..359] unwritten.
// ---------------------------------------------------------------------------

#define BD 256
#define B_SZ 8
#define C_SZ 7
#define T_SZ 45
#define D_SZ 5120
#define D4_SZ (D_SZ / 4)          // 1280
#define S_SZ 4096
#define SPLITS 21
#define STREAM_CTAS (5 * B_SZ * SPLITS)   // 840
#define SERIES_CTAS (D_SZ / BD)           // 20
#define TOTAL_CTAS (STREAM_CTAS + SERIES_CTAS) // 860 < 888 (148*6)

__device__ float4 g_part[SPLITS * B_SZ * D4_SZ];       // mean partial sums (3.44 MB)
__device__ float  g_emb [B_SZ * D_SZ];                 // un-normalized projection
__device__ float  g_ssq_part[SERIES_CTAS * B_SZ];      // per-CTA per-batch sumsq

// ============================================================================
// K1: 840 streaming CTAs (mean partials) + 20 series CTAs (prep + project).
// ============================================================================
__global__ __launch_bounds__(BD, 6) void fused_kernel(
    const float* __restrict__ hs,
    const float* __restrict__ x,
    const float* __restrict__ W,
    const float* __restrict__ bias,
    float* __restrict__ out_xnorm)
{
    const int cta = blockIdx.x;
    const int tid = threadIdx.x;

    if (cta < STREAM_CTAS) {
        // ---------------- streaming: sum a slice of hidden_states -----------
        const int dchunk = cta % 5;
        const int b      = (cta / 5) % B_SZ;
        const int z      = cta / (5 * B_SZ);
        const int d4     = dchunk * BD + tid;

        const int s0 = (int)(((long long)z       * S_SZ) / SPLITS);
        const int s1 = (int)(((long long)(z + 1) * S_SZ) / SPLITS);
        const int rows = s1 - s0;

        const float4* p = reinterpret_cast<const float4*>(hs)
                        + (size_t)b * S_SZ * D4_SZ + (size_t)s0 * D4_SZ + d4;

        float4 a0 = make_float4(0.f, 0.f, 0.f, 0.f);
        float4 a1 = make_float4(0.f, 0.f, 0.f, 0.f);

        int r = 0;
        #pragma unroll 4
        for (; r + 1 < rows; r += 2) {
            float4 v0 = __ldcs(p + (size_t)r       * D4_SZ);
            float4 v1 = __ldcs(p + (size_t)(r + 1) * D4_SZ);
            a0.x += v0.x; a0.y += v0.y; a0.z += v0.z; a0.w += v0.w;
            a1.x += v1.x; a1.y += v1.y; a1.z += v1.z; a1.w += v1.w;
        }
        for (; r < rows; r++) {
            float4 v = __ldcs(p + (size_t)r * D4_SZ);
            a0.x += v.x; a0.y += v.y; a0.z += v.z; a0.w += v.w;
        }

        float4 out;
        out.x = a0.x + a1.x; out.y = a0.y + a1.y;
        out.z = a0.z + a1.z; out.w = a0.w + a1.w;
        g_part[((size_t)z * B_SZ + b) * D4_SZ + d4] = out;
    } else {
        // ---------------- series branch (20 CTAs, hidden under the stream) --
        const int sid = cta - STREAM_CTAS;        // 0..19
        const int d   = sid * BD + tid;           // this CTA's d-range

        __shared__ float sx[B_SZ * C_SZ * T_SZ];  // whole x (10 KB)
        __shared__ float smn[B_SZ * C_SZ], smx[B_SZ * C_SZ];
        __shared__ float s_sm[B_SZ * T_SZ];       // 360 entries
        __shared__ float sred[8][B_SZ];

        const int TOT = B_SZ * C_SZ * T_SZ;       // 2520
        for (int i = tid; i < TOT; i += BD) sx[i] = x[i];
        __syncthreads();

        // per-(b,c) min/max: 56 scans of 45
        if (tid < B_SZ * C_SZ) {
            const float* row = sx + tid * T_SZ;
            float mn = row[0], mx = row[0];
            #pragma unroll
            for (int t = 1; t < T_SZ; t++) {
                float v = row[t];
                mn = fminf(mn, v); mx = fmaxf(mx, v);
            }
            smn[tid] = mn; smx[tid] = mx;
        }
        __syncthreads();

        // CTA 0 alone writes x_normalized (tiny)
        if (sid == 0) {
            for (int i = tid; i < TOT; i += BD) {
                int bc = i / T_SZ;
                float v = sx[i], mn = smn[bc], mx = smx[bc];
                out_xnorm[i] = (mx > mn) ? (v - mn) / (mx - mn) : v;
            }
        }

        // channel means: 360 entries > 256 threads -> MUST be a strided loop
        for (int i = tid; i < B_SZ * T_SZ; i += BD) {
            int b = i / T_SZ, t = i % T_SZ;
            float s = 0.f;
            #pragma unroll
            for (int c = 0; c < C_SZ; c++)
                s += sx[(b * C_SZ + c) * T_SZ + t];
            s_sm[i] = s * (1.0f / (float)C_SZ);
        }
        __syncthreads();

        // projection: this thread owns column d; batches in 2 groups of 4
        const float bv = bias[d];
        const int warp = tid >> 5, lane = tid & 31;

        #pragma unroll
        for (int g = 0; g < 2; g++) {
            float acc0 = bv, acc1 = bv, acc2 = bv, acc3 = bv;
            const float* m0 = s_sm + (g * 4 + 0) * T_SZ;
            const float* m1 = s_sm + (g * 4 + 1) * T_SZ;
            const float* m2 = s_sm + (g * 4 + 2) * T_SZ;
            const float* m3 = s_sm + (g * 4 + 3) * T_SZ;
            #pragma unroll
            for (int t = 0; t < T_SZ; t++) {
                const float w = W[(size_t)t * D_SZ + d];
                acc0 = fmaf(m0[t], w, acc0);
                acc1 = fmaf(m1[t], w, acc1);
                acc2 = fmaf(m2[t], w, acc2);
                acc3 = fmaf(m3[t], w, acc3);
            }
            g_emb[(size_t)(g * 4 + 0) * D_SZ + d] = acc0;
            g_emb[(size_t)(g * 4 + 1) * D_SZ + d] = acc1;
            g_emb[(size_t)(g * 4 + 2) * D_SZ + d] = acc2;
            g_emb[(size_t)(g * 4 + 3) * D_SZ + d] = acc3;

            const float sq[4] = {acc0 * acc0, acc1 * acc1, acc2 * acc2, acc3 * acc3};
            #pragma unroll
            for (int j = 0; j < 4; j++) {
                float v = sq[j];
                #pragma unroll
                for (int off = 16; off; off >>= 1)
                    v += __shfl_xor_sync(0xffffffffu, v, off);
                if (lane == 0) sred[warp][g * 4 + j] = v;
            }
            __syncthreads();
            if (tid < 4) {
                int b = g * 4 + tid;
                float tot = 0.f;
                #pragma unroll
                for (int w2 = 0; w2 < 8; w2++) tot += sred[w2][b];
                g_ssq_part[sid * B_SZ + b] = tot;
            }
            __syncthreads();
        }
    }
}

// ============================================================================
// K2: combine. out_fused[b,d] = g_emb[b,d] * inv_norm(b) + mean(hidden).
//     grid(5, 8), 256 threads. Reads g_part (3.4 MB) + g_emb.
// ============================================================================
__global__ __launch_bounds__(BD) void combine_kernel(
    float* __restrict__ out_fused)
{
    const int b  = blockIdx.y;
    const int d4 = blockIdx.x * BD + threadIdx.x;

    __shared__ float s_inv;
    if (threadIdx.x == 0) {
        float ssq = 0.f;
        #pragma unroll
        for (int s = 0; s < SERIES_CTAS; s++)
            ssq += g_ssq_part[s * B_SZ + b];
        s_inv = 1.0f / fmaxf(sqrtf(ssq), 1e-12f);
    }
    __syncthreads();
    const float inv = s_inv;

    float4 acc = make_float4(0.f, 0.f, 0.f, 0.f);
    #pragma unroll
    for (int z = 0; z < SPLITS; z++) {
        float4 v = g_part[((size_t)z * B_SZ + b) * D4_SZ + d4];
        acc.x += v.x; acc.y += v.y; acc.z += v.z; acc.w += v.w;
    }

    const float invS = 1.0f / (float)S_SZ;
    const float4 e = reinterpret_cast<const float4*>(g_emb)[(size_t)b * D4_SZ + d4];

    float4 o;
    o.x = fmaf(e.x, inv, acc.x * invS);
    o.y = fmaf(e.y, inv, acc.y * invS);
    o.z = fmaf(e.z, inv, acc.z * invS);
    o.w = fmaf(e.w, inv, acc.w * invS);
    reinterpret_cast<float4*>(out_fused)[(size_t)b * D4_SZ + d4] = o;
}

// ============================================================================
extern "C" void kernel_launch(void* const* d_in, const int* in_sizes, int n_in,
                              void* d_out, int out_size)
{
    const float* x    = (const float*)d_in[0];
    const float* hs   = (const float*)d_in[1];
    const float* W    = (const float*)d_in[2];
    const float* bias = (const float*)d_in[3];

    float* out_fused = (float*)d_out;                       // [B, D]
    float* out_xnorm = (float*)d_out + (size_t)B_SZ * D_SZ; // [B, C, T]

    fused_kernel<<<TOTAL_CTAS, BD>>>(hs, x, W, bias, out_xnorm);
    combine_kernel<<<dim3(D4_SZ / BD, B_SZ), BD>>>(out_fused);
}